// round 7
// baseline (speedup 1.0000x reference)
#include <cuda_runtime.h>
#include <cstdint>

#define Nn 2048
#define Dd 64
#define Vv 2048
#define TB 128                      // pair tile dim
#define NT (Nn / TB)                // 16
#define NTILES (NT * (NT + 1) / 2)  // 136 triangle tiles
#define PADK 33                     // float2 row stride (pad) -> conflict-free
#define NTHR 1024
#define MAXBLK 1024                 // k_pre max-reduction blocks

// Scratch (no allocations -> __device__ globals). All overwritten per call.
__device__ float g_part[MAXBLK];            // per-block maxes of map
__device__ float g_rowsum[Nn];              // S[i] = sum_d emb[i][d]
__device__ float g_psum[NTILES], g_pcnt[NTILES];
__device__ unsigned g_ctr;                  // zero-init; last block resets to 0

// ---------------------------------------------------------------------------
__device__ __forceinline__ void cpa4(uint32_t dst, const float* src) {
    asm volatile("cp.async.ca.shared.global [%0], [%1], 4;" :: "r"(dst), "l"(src));
}

// ---------------------------------------------------------------------------
// blocks 0..1023: map max (256 thr x 4 float4 = 16KB/block, MLP 4)
// blocks 1024..1031: row sums of emb (one row per thread)
__global__ __launch_bounds__(256) void k_pre(const float4* __restrict__ mapd,
                                             const float4* __restrict__ emb) {
    int bid = blockIdx.x, tid = threadIdx.x;
    if (bid < MAXBLK) {
        const float4* p = mapd + (size_t)bid * 1024;
        float4 x0 = p[tid];
        float4 x1 = p[tid + 256];
        float4 x2 = p[tid + 512];
        float4 x3 = p[tid + 768];
        float v = fmaxf(fmaxf(fmaxf(x0.x, x0.y), fmaxf(x0.z, x0.w)),
                        fmaxf(fmaxf(x1.x, x1.y), fmaxf(x1.z, x1.w)));
        v = fmaxf(v, fmaxf(fmaxf(fmaxf(x2.x, x2.y), fmaxf(x2.z, x2.w)),
                           fmaxf(fmaxf(x3.x, x3.y), fmaxf(x3.z, x3.w))));
#pragma unroll
        for (int o = 16; o; o >>= 1) v = fmaxf(v, __shfl_xor_sync(0xffffffffu, v, o));
        __shared__ float sred[8];
        int lane = tid & 31, w = tid >> 5;
        if (lane == 0) sred[w] = v;
        __syncthreads();
        if (tid == 0) {
            float m = sred[0];
#pragma unroll
            for (int i = 1; i < 8; i++) m = fmaxf(m, sred[i]);
            g_part[bid] = m;
        }
    } else {
        int row = (bid - MAXBLK) * 256 + tid;   // 2048 rows
        const float4* e = emb + row * (Dd / 4);
        float s = 0.0f;
#pragma unroll
        for (int k = 0; k < Dd / 4; k++) {
            float4 x = e[k];
            s += (x.x + x.y) + (x.z + x.w);
        }
        g_rowsum[row] = s;
    }
}

// ---------------------------------------------------------------------------
extern __shared__ unsigned long long smem_raw[];

// 1024 threads, 128x128 tile; thread (tx=tid&31, ty=tid>>5) owns rows
// ty+32r (r<4), cols tx+32c (c<4). Inner op per element: FMNMX (alu) +
// FADD (fma) -- balanced dual-pipe, Sum|a-b| = 2*Sum max - S_i - S_j.
// tree/map gathers issued via cp.async before the mainloop (latency hidden).
// Last finishing block folds the global reduction (no extra kernel).
__global__ __launch_bounds__(NTHR, 1) void k_main(const int* __restrict__ ids,
                                                  const float2* __restrict__ emb,
                                                  const float* __restrict__ tree,
                                                  const float* __restrict__ mapd,
                                                  float* __restrict__ out) {
    int tid = threadIdx.x;
    int t = blockIdx.x, bi = 0;
    while (t >= NT - bi) { t -= NT - bi; bi++; }
    int bj = bi + t;
    int ibase = bi * TB, jbase = bj * TB;
    bool offdiag = (bi != bj);

    float2* sA = (float2*)smem_raw;                 // [128][PADK]
    float2* sB = sA + TB * PADK;
    int*   sIdI = (int*)(sB + TB * PADK);
    int*   sIdJ = sIdI + TB;
    float* sSA  = (float*)(sIdJ + TB);              // row sums i-tile
    float* sSB  = sSA + TB;                         // row sums j-tile
    float* sSc  = sSB + TB;                         // [0] = 0.5/max
    float* sMT  = sSc + 4;                          // [16][1024] tree gathers
    float* sMM  = sMT + 16 * NTHR;                  // [16][1024] map gathers
    __shared__ float sred[64];

    int tx = tid & 31, ty = tid >> 5;

    // role-split preload (ids needed before gathers can be issued)
    if (tid < TB)            sIdI[tid] = ids[ibase + tid];
    else if (tid < 2 * TB)   sIdJ[tid - TB] = ids[jbase + tid - TB];
    else if (tid < 3 * TB)   sSA[tid - 2 * TB] = g_rowsum[ibase + tid - 2 * TB];
    else if (tid < 4 * TB)   sSB[tid - 3 * TB] = g_rowsum[jbase + tid - 3 * TB];
    if (ty == 31) {          // one warp reduces the 1024 partial maxes
        float v = 0.0f;
        for (int k = tx; k < MAXBLK; k += 32) v = fmaxf(v, g_part[k]);
#pragma unroll
        for (int o = 16; o; o >>= 1) v = fmaxf(v, __shfl_xor_sync(0xffffffffu, v, o));
        if (tx == 0) sSc[0] = 0.5f / v;
    }
    __syncthreads();

    // issue all metric gathers now; they complete under the mainloop
    {
        uint32_t dT = (uint32_t)__cvta_generic_to_shared(sMT) + tid * 4u;
        uint32_t dM = (uint32_t)__cvta_generic_to_shared(sMM) + tid * 4u;
#pragma unroll
        for (int r = 0; r < 4; r++) {
            int off0 = sIdI[ty + 32 * r] * Vv;
#pragma unroll
            for (int c = 0; c < 4; c++) {
                int idx = off0 + sIdJ[tx + 32 * c];
                uint32_t po = (uint32_t)(r * 4 + c) * (NTHR * 4u);
                cpa4(dT + po, tree + idx);
                cpa4(dM + po, mapd + idx);
            }
        }
        asm volatile("cp.async.commit_group;");
    }

    // embedding tiles (coalesced)
    for (int x = tid; x < TB * 32; x += NTHR) {
        int row = x >> 5, k2 = x & 31;
        sA[row * PADK + k2] = emb[(ibase + row) * 32 + k2];
        sB[row * PADK + k2] = emb[(jbase + row) * 32 + k2];
    }
    __syncthreads();

    float acc[4][4][2];
#pragma unroll
    for (int r = 0; r < 4; r++)
#pragma unroll
        for (int c = 0; c < 4; c++) { acc[r][c][0] = 0.0f; acc[r][c][1] = 0.0f; }

    const float2* sArow = sA + ty * PADK;
    const float2* sBrow = sB + tx * PADK;

#pragma unroll 4
    for (int k2 = 0; k2 < 32; k2++) {
        float2 b2[4];
#pragma unroll
        for (int c = 0; c < 4; c++) b2[c] = sBrow[(32 * c) * PADK + k2];
#pragma unroll
        for (int r = 0; r < 4; r++) {
            float2 a = sArow[(32 * r) * PADK + k2];
#pragma unroll
            for (int c = 0; c < 4; c++) {
                acc[r][c][0] += fmaxf(a.x, b2[c].x);   // FMNMX (alu) + FADD (fma)
                acc[r][c][1] += fmaxf(a.y, b2[c].y);
            }
        }
    }

    asm volatile("cp.async.wait_group 0;" ::: "memory");

    // epilogue: ed = (2*sum(max) - S_i - S_j)/64 ; metric = 0.5*t + sc*m
    float sc = sSc[0];
    float loss = 0.0f, cnt = 0.0f;
    const float inv64 = 1.0f / 64.0f;
#pragma unroll
    for (int r = 0; r < 4; r++) {
        int ir = ty + 32 * r;
        int idi = sIdI[ir];
        int gi  = ibase + ir;
        float Si = sSA[ir];
#pragma unroll
        for (int c = 0; c < 4; c++) {
            int jc = tx + 32 * c;
            int idj = sIdJ[jc];
            int gj  = jbase + jc;
            if ((offdiag || gi < gj) && idi != idj) {
                float mx = acc[r][c][0] + acc[r][c][1];
                float ed = (2.0f * mx - Si - sSB[jc]) * inv64;
                int p = (r * 4 + c) * NTHR + tid;
                float metric = fmaf(sc, sMM[p], 0.5f * sMT[p]);
                loss += fabsf(ed - metric);
                cnt += 1.0f;
            }
        }
    }

#pragma unroll
    for (int o = 16; o; o >>= 1) {
        loss += __shfl_xor_sync(0xffffffffu, loss, o);
        cnt  += __shfl_xor_sync(0xffffffffu, cnt, o);
    }
    int lane = tid & 31, w = tid >> 5;
    if (lane == 0) { sred[w] = loss; sred[32 + w] = cnt; }
    __syncthreads();
    if (tid == 0) {
        float L = 0.0f, C = 0.0f;
#pragma unroll
        for (int i = 0; i < 32; i++) { L += sred[i]; C += sred[32 + i]; }
        g_psum[blockIdx.x] = L;
        g_pcnt[blockIdx.x] = C;
        __threadfence();
        unsigned done = atomicAdd(&g_ctr, 1u);
        sred[0] = (done == NTILES - 1) ? 1.0f : 0.0f;
    }
    __syncthreads();
    if (sred[0] != 0.0f) {            // last block folds the final reduction
        __threadfence();
        float L = 0.0f, C = 0.0f;
        if (tid < NTILES) {
            L = *((volatile float*)g_psum + tid);
            C = *((volatile float*)g_pcnt + tid);
        }
#pragma unroll
        for (int o = 16; o; o >>= 1) {
            L += __shfl_xor_sync(0xffffffffu, L, o);
            C += __shfl_xor_sync(0xffffffffu, C, o);
        }
        if (lane == 0) { sred[w] = L; sred[32 + w] = C; }
        __syncthreads();
        if (tid == 0) {
            float LL = 0.0f, CC = 0.0f;
#pragma unroll
            for (int i = 0; i < 5; i++) { LL += sred[i]; CC += sred[32 + i]; }
            out[0] = LL / CC;
            g_ctr = 0u;               // self-reset for next graph replay
        }
    }
}

// ---------------------------------------------------------------------------
extern "C" void kernel_launch(void* const* d_in, const int* in_sizes, int n_in,
                              void* d_out, int out_size) {
    const int*   ids  = (const int*)d_in[0];
    const float* emb  = (const float*)d_in[1];
    const float* tree = (const float*)d_in[2];
    const float* mapd = (const float*)d_in[3];
    float* out = (float*)d_out;

    // smem: tiles 67584 + ids/rowsums/sc 2064 + 16 + gather planes 131072
    const int SMEM_BYTES = 2 * TB * PADK * 8 + 4 * TB * 4 + 16 + 32 * NTHR * 4;
    cudaFuncSetAttribute(k_main, cudaFuncAttributeMaxDynamicSharedMemorySize,
                         SMEM_BYTES);

    k_pre<<<MAXBLK + Nn / 256, 256>>>((const float4*)mapd, (const float4*)emb);
    k_main<<<NTILES, NTHR, SMEM_BYTES>>>(ids, (const float2*)emb, tree, mapd, out);
}